// round 9
// baseline (speedup 1.0000x reference)
#include <cuda_runtime.h>
#include <cuda_bf16.h>

#define FEAT 384
#define FEAT4 (FEAT / 4)   // 96 float4 per row
#define ALPHA 0.2f

// Cross-block reduction state. Must be zero at the start of every launch;
// the last block restores it to zero, so graph replays are deterministic.
__device__ float        g_sum   = 0.0f;
__device__ unsigned int g_count = 0u;

__global__ __launch_bounds__(256, 5) void triplet_kernel(
    const float4* __restrict__ anchor,
    const float4* __restrict__ positive,
    const float4* __restrict__ negative,
    const float*  __restrict__ W,
    float* __restrict__ out,
    int B)
{
    __shared__ float expw[FEAT];
    __shared__ float block_sum;

    for (int i = threadIdx.x; i < FEAT; i += blockDim.x)
        expw[i] = expf(W[i]);
    if (threadIdx.x == 0) block_sum = 0.0f;
    __syncthreads();

    const int lane  = threadIdx.x & 31;
    const int warp  = threadIdx.x >> 5;
    const int wpb   = blockDim.x >> 5;
    const int gwarp = blockIdx.x * wpb + warp;
    const int nwarp = gridDim.x * wpb;

    // Register-resident exp(W): this lane's 3 float4, reused every row.
    float4 wv[3];
    #pragma unroll
    for (int j = 0; j < 3; j++)
        wv[j] = *reinterpret_cast<const float4*>(&expw[(j * 32 + lane) * 4]);

    float acc = 0.0f;   // meaningful on lane 0

    // ---- Software-pipelined row loop ----
    // Loads for row r+1 are issued BEFORE row r's shfl chain, so the 5-deep
    // dependent shuffle tree overlaps with in-flight memory instead of
    // leaving the warp load-idle. Registers are reused (no extra liveness).
    int row = gwarp;                       // every warp has >= 1 row (5920 << B)

    float4 av[3], pv[3], nv[3];
    #pragma unroll
    for (int j = 0; j < 3; j++) {
        const int idx = j * 32 + lane;
        av[j] = __ldg(anchor   + (long long)row * FEAT4 + idx);
        pv[j] = __ldg(positive + (long long)row * FEAT4 + idx);
        nv[j] = __ldg(negative + (long long)row * FEAT4 + idx);
    }

    while (true) {
        // FMA section for the current row (two accumulators halve the chain).
        float da = 0.0f, db = 0.0f;
        #pragma unroll
        for (int j = 0; j < 3; j++) {
            float dp, dn;
            dp = av[j].x - pv[j].x; dn = av[j].x - nv[j].x; da += wv[j].x * (dp * dp - dn * dn);
            dp = av[j].y - pv[j].y; dn = av[j].y - nv[j].y; db += wv[j].y * (dp * dp - dn * dn);
            dp = av[j].z - pv[j].z; dn = av[j].z - nv[j].z; da += wv[j].z * (dp * dp - dn * dn);
            dp = av[j].w - pv[j].w; dn = av[j].w - nv[j].w; db += wv[j].w * (dp * dp - dn * dn);
        }
        float d = da + db;

        // Prefetch next row's data (register reuse; issues before the shfls).
        const int next = row + nwarp;
        const bool more = next < B;
        if (more) {
            #pragma unroll
            for (int j = 0; j < 3; j++) {
                const int idx = j * 32 + lane;
                av[j] = __ldg(anchor   + (long long)next * FEAT4 + idx);
                pv[j] = __ldg(positive + (long long)next * FEAT4 + idx);
                nv[j] = __ldg(negative + (long long)next * FEAT4 + idx);
            }
        }

        // Shuffle reduction overlaps with the in-flight prefetch.
        #pragma unroll
        for (int off = 16; off > 0; off >>= 1)
            d += __shfl_xor_sync(0xFFFFFFFFu, d, off);

        if (lane == 0)
            acc += fmaxf(d + ALPHA, 0.0f);

        if (!more) break;
        row = next;
    }

    if (lane == 0)
        atomicAdd(&block_sum, acc);
    __syncthreads();

    // Last-block-done: single kernel, no separate zero-init launch.
    if (threadIdx.x == 0) {
        atomicAdd(&g_sum, block_sum);
        __threadfence();
        const unsigned int prev = atomicAdd(&g_count, 1u);
        if (prev == gridDim.x - 1) {
            out[0] = g_sum * (1.0f / (float)B);
            // Restore globals so the next (graph-replayed) launch starts clean.
            g_sum   = 0.0f;
            g_count = 0u;
            __threadfence();
        }
    }
}

extern "C" void kernel_launch(void* const* d_in, const int* in_sizes, int n_in,
                              void* d_out, int out_size) {
    const float4* anchor   = (const float4*)d_in[0];
    const float4* positive = (const float4*)d_in[1];
    const float4* negative = (const float4*)d_in[2];
    const float*  W        = (const float*)d_in[3];
    float* out = (float*)d_out;

    const int B = in_sizes[0] / FEAT;   // 131072

    const int threads = 256;
    const int blocks  = 740;            // 148 SMs * 5 resident blocks -> one exact wave
    triplet_kernel<<<blocks, threads>>>(anchor, positive, negative, W, out, B);
}

// round 10
// speedup vs baseline: 1.3061x; 1.3061x over previous
#include <cuda_runtime.h>
#include <cuda_bf16.h>

#define FEAT 384
#define FEAT4 (FEAT / 4)   // 96 float4 per row
#define ALPHA 0.2f
#define CHUNK 8            // rows per ticket (131072 / 8 = 16384 tickets)

// Cross-block state. Must be zero at the start of every launch; the last
// block restores all of it, so graph replays are deterministic.
__device__ float        g_sum    = 0.0f;
__device__ unsigned int g_count  = 0u;
__device__ unsigned int g_ticket = 0u;

__global__ __launch_bounds__(256, 5) void triplet_kernel(
    const float4* __restrict__ anchor,
    const float4* __restrict__ positive,
    const float4* __restrict__ negative,
    const float*  __restrict__ W,
    float* __restrict__ out,
    int B)
{
    __shared__ float expw[FEAT];
    __shared__ float block_sum;

    for (int i = threadIdx.x; i < FEAT; i += blockDim.x)
        expw[i] = expf(W[i]);
    if (threadIdx.x == 0) block_sum = 0.0f;
    __syncthreads();

    const int lane = threadIdx.x & 31;

    // Register-resident exp(W): this lane's 3 float4, reused every row.
    float4 wv[3];
    #pragma unroll
    for (int j = 0; j < 3; j++)
        wv[j] = *reinterpret_cast<const float4*>(&expw[(j * 32 + lane) * 4]);

    float acc = 0.0f;   // meaningful on lane 0

    // Dynamic ticket scheduler: each warp grabs CHUNK consecutive rows.
    // Removes the static 22-vs-23 rows/warp imbalance that paced the chip
    // at the 23-row warps' speed.
    const unsigned int n_tickets = (unsigned int)(B / CHUNK);
    while (true) {
        unsigned int t;
        if (lane == 0) t = atomicAdd(&g_ticket, 1u);
        t = __shfl_sync(0xFFFFFFFFu, t, 0);
        if (t >= n_tickets) break;

        const int row0 = (int)t * CHUNK;
        #pragma unroll 1
        for (int r = 0; r < CHUNK; r++) {
            const long long row = row0 + r;
            const float4* ar = anchor   + row * FEAT4;
            const float4* pr = positive + row * FEAT4;
            const float4* nr = negative + row * FEAT4;

            // Two independent accumulators halve the serial FMA chain.
            float da = 0.0f, db = 0.0f;
            #pragma unroll
            for (int j = 0; j < 3; j++) {
                const int idx = j * 32 + lane;
                const float4 av = __ldg(&ar[idx]);
                const float4 pv = __ldg(&pr[idx]);
                const float4 nv = __ldg(&nr[idx]);

                float dp, dn;
                dp = av.x - pv.x; dn = av.x - nv.x; da += wv[j].x * (dp * dp - dn * dn);
                dp = av.y - pv.y; dn = av.y - nv.y; db += wv[j].y * (dp * dp - dn * dn);
                dp = av.z - pv.z; dn = av.z - nv.z; da += wv[j].z * (dp * dp - dn * dn);
                dp = av.w - pv.w; dn = av.w - nv.w; db += wv[j].w * (dp * dp - dn * dn);
            }
            float d = da + db;

            #pragma unroll
            for (int off = 16; off > 0; off >>= 1)
                d += __shfl_xor_sync(0xFFFFFFFFu, d, off);

            if (lane == 0)
                acc += fmaxf(d + ALPHA, 0.0f);
        }
    }

    if (lane == 0)
        atomicAdd(&block_sum, acc);
    __syncthreads();

    // Last-block-done: single kernel, no separate zero-init launch.
    if (threadIdx.x == 0) {
        atomicAdd(&g_sum, block_sum);
        __threadfence();
        const unsigned int prev = atomicAdd(&g_count, 1u);
        if (prev == gridDim.x - 1) {
            out[0] = g_sum * (1.0f / (float)B);
            // Restore globals so the next (graph-replayed) launch starts clean.
            g_sum    = 0.0f;
            g_count  = 0u;
            g_ticket = 0u;
            __threadfence();
        }
    }
}

extern "C" void kernel_launch(void* const* d_in, const int* in_sizes, int n_in,
                              void* d_out, int out_size) {
    const float4* anchor   = (const float4*)d_in[0];
    const float4* positive = (const float4*)d_in[1];
    const float4* negative = (const float4*)d_in[2];
    const float*  W        = (const float*)d_in[3];
    float* out = (float*)d_out;

    const int B = in_sizes[0] / FEAT;   // 131072

    const int threads = 256;
    const int blocks  = 740;            // 148 SMs * 5 resident blocks -> one exact wave
    triplet_kernel<<<blocks, threads>>>(anchor, positive, negative, W, out, B);
}

// round 11
// speedup vs baseline: 1.3967x; 1.0694x over previous
#include <cuda_runtime.h>
#include <cuda_bf16.h>

#define FEAT 384
#define FEAT4 (FEAT / 4)   // 96 float4 per row
#define ALPHA 0.2f

// Cross-block reduction state. Must be zero at the start of every launch;
// the last block restores it to zero, so graph replays are deterministic.
__device__ float        g_sum   = 0.0f;
__device__ unsigned int g_count = 0u;

__global__ __launch_bounds__(256, 5) void triplet_kernel(
    const float4* __restrict__ anchor,
    const float4* __restrict__ positive,
    const float4* __restrict__ negative,
    const float*  __restrict__ W,
    float* __restrict__ out,
    int B)
{
    __shared__ float expw[FEAT];
    __shared__ float block_sum;

    for (int i = threadIdx.x; i < FEAT; i += blockDim.x)
        expw[i] = expf(W[i]);
    if (threadIdx.x == 0) block_sum = 0.0f;
    __syncthreads();

    const int lane  = threadIdx.x & 31;
    const int warp  = threadIdx.x >> 5;
    const int wpb   = blockDim.x >> 5;
    const int gwarp = blockIdx.x * wpb + warp;
    const int nwarp = gridDim.x * wpb;

    // Register-resident exp(W): this lane's 3 float4, reused every row.
    float4 wv[3];
    #pragma unroll
    for (int j = 0; j < 3; j++)
        wv[j] = *reinterpret_cast<const float4*>(&expw[(j * 32 + lane) * 4]);

    float acc = 0.0f;   // meaningful on lane 0

    for (int row = gwarp; row < B; row += nwarp) {
        const float4* ar = anchor   + (long long)row * FEAT4;
        const float4* pr = positive + (long long)row * FEAT4;
        const float4* nr = negative + (long long)row * FEAT4;

        // Two independent accumulators halve the serial FMA chain.
        float da = 0.0f, db = 0.0f;
        #pragma unroll
        for (int j = 0; j < 3; j++) {
            const int idx = j * 32 + lane;
            const float4 av = __ldg(&ar[idx]);
            const float4 pv = __ldg(&pr[idx]);
            const float4 nv = __ldg(&nr[idx]);

            float dp, dn;
            dp = av.x - pv.x; dn = av.x - nv.x; da += wv[j].x * (dp * dp - dn * dn);
            dp = av.y - pv.y; dn = av.y - nv.y; db += wv[j].y * (dp * dp - dn * dn);
            dp = av.z - pv.z; dn = av.z - nv.z; da += wv[j].z * (dp * dp - dn * dn);
            dp = av.w - pv.w; dn = av.w - nv.w; db += wv[j].w * (dp * dp - dn * dn);
        }
        float d = da + db;

        #pragma unroll
        for (int off = 16; off > 0; off >>= 1)
            d += __shfl_xor_sync(0xFFFFFFFFu, d, off);

        if (lane == 0)
            acc += fmaxf(d + ALPHA, 0.0f);
    }

    if (lane == 0)
        atomicAdd(&block_sum, acc);
    __syncthreads();

    // Last-block-done: single kernel, no separate zero-init launch.
    if (threadIdx.x == 0) {
        atomicAdd(&g_sum, block_sum);
        __threadfence();
        const unsigned int prev = atomicAdd(&g_count, 1u);
        if (prev == gridDim.x - 1) {
            out[0] = g_sum * (1.0f / (float)B);
            // Restore globals so the next (graph-replayed) launch starts clean.
            g_sum   = 0.0f;
            g_count = 0u;
            __threadfence();
        }
    }
}

extern "C" void kernel_launch(void* const* d_in, const int* in_sizes, int n_in,
                              void* d_out, int out_size) {
    const float4* anchor   = (const float4*)d_in[0];
    const float4* positive = (const float4*)d_in[1];
    const float4* negative = (const float4*)d_in[2];
    const float*  W        = (const float*)d_in[3];
    float* out = (float*)d_out;

    const int B = in_sizes[0] / FEAT;   // 131072

    const int threads = 256;
    const int blocks  = 740;            // 148 SMs * 5 resident blocks -> one exact wave
    triplet_kernel<<<blocks, threads>>>(anchor, positive, negative, W, out, B);
}